// round 6
// baseline (speedup 1.0000x reference)
#include <cuda_runtime.h>
#include <cuda_bf16.h>
#include <cstdint>

// ---------------------------------------------------------------------------
// Problem constants
// ---------------------------------------------------------------------------
static constexpr int Nn = 8192;
static constexpr int Pp = 8192;
static constexpr int Dd = 256;   // K
static constexpr int Cc = 1000;

// Tiling
static constexpr int TM = 128;               // CTA tile M
static constexpr int TN = 128;               // CTA tile N
static constexpr int COL_SPLITS = 2;
static constexpr int COLS_PER_CTA = Pp / COL_SPLITS;       // 4096
static constexpr int NT = COLS_PER_CTA / TN;               // 32 tiles per CTA
static constexpr int ROW_TILES = Nn / TM;                  // 64
static constexpr int NUM_K_STEPS = Dd / 16;                // 16
static constexpr int NTHREADS = 512;                        // 16 warps: 4M x 4N

// SMEM: A tile / B tiles are 128 rows x 512B, stored as 4 blocks of
// [128 rows x 128B], SW128-swizzled within each block.
static constexpr int TILE_BYTES  = TM * Dd * 2;            // 65536
static constexpr int BLOCK_BYTES = 16384;
static constexpr int SMEM_A  = 0;
static constexpr int SMEM_B0 = SMEM_A + TILE_BYTES;
static constexpr int SMEM_B1 = SMEM_B0 + TILE_BYTES;
static constexpr int SMEM_LP = SMEM_B1 + TILE_BYTES;       // 2 x 128 ints
static constexpr int SMEM_TOTAL = SMEM_LP + 2 * TN * 4;    // 197632

// ---------------------------------------------------------------------------
// Device scratch
// ---------------------------------------------------------------------------
__device__ __nv_bfloat16 g_xn[Nn * Dd];
__device__ __nv_bfloat16 g_yn[Pp * Dd];
__device__ float g_ap[Nn];
__device__ float g_an[Nn];
__device__ float g_pc[Nn];
__device__ float g_hc[Nn];

// ---------------------------------------------------------------------------
// PTX helpers (compute_100-safe: cp.async, ldmatrix, mma.sync only)
// ---------------------------------------------------------------------------
__device__ __forceinline__ uint32_t smem_u32(const void* p) {
    uint32_t a;
    asm("{ .reg .u64 t; cvta.to.shared.u64 t, %1; cvt.u32.u64 %0, t; }" : "=r"(a) : "l"(p));
    return a;
}
__device__ __forceinline__ uint32_t swz128(uint32_t off) {
    return off ^ ((off >> 3) & 0x70);
}
__device__ __forceinline__ void cp_async16(uint32_t dst, const void* src) {
    asm volatile("cp.async.cg.shared.global [%0], [%1], 16;" :: "r"(dst), "l"(src));
}
#define CP_COMMIT()  asm volatile("cp.async.commit_group;" ::: "memory")
#define CP_WAIT(n)   asm volatile("cp.async.wait_group %0;" :: "n"(n) : "memory")

__device__ __forceinline__ void ldsm_x4(uint32_t* r, uint32_t addr) {
    asm volatile("ldmatrix.sync.aligned.m8n8.x4.shared.b16 {%0,%1,%2,%3}, [%4];"
                 : "=r"(r[0]), "=r"(r[1]), "=r"(r[2]), "=r"(r[3]) : "r"(addr));
}
__device__ __forceinline__ void mma_bf16(float* d, const uint32_t* a,
                                         uint32_t b0, uint32_t b1) {
    asm volatile(
        "mma.sync.aligned.m16n8k16.row.col.f32.bf16.bf16.f32 "
        "{%0,%1,%2,%3}, {%4,%5,%6,%7}, {%8,%9}, {%0,%1,%2,%3};"
        : "+f"(d[0]), "+f"(d[1]), "+f"(d[2]), "+f"(d[3])
        : "r"(a[0]), "r"(a[1]), "r"(a[2]), "r"(a[3]), "r"(b0), "r"(b1));
}

// smem tile element address: (row, kbyte) with kbyte in [0,512)
__device__ __forceinline__ uint32_t tile_addr(uint32_t base, int row, int kbyte) {
    return base + (kbyte >> 7) * BLOCK_BYTES + swz128(row * 128 + (kbyte & 127));
}

// ---------------------------------------------------------------------------
// init: zero accumulators + output
// ---------------------------------------------------------------------------
__global__ void init_kernel(float* __restrict__ out) {
    int i = blockIdx.x * blockDim.x + threadIdx.x;
    if (i < Nn) { g_ap[i] = 0.f; g_an[i] = 0.f; g_pc[i] = 0.f; g_hc[i] = 0.f; }
    if (i == 0) out[0] = 0.f;
}

// ---------------------------------------------------------------------------
// normalize rows of x (Nn) and y (Pp) -> bf16 scratch
// ---------------------------------------------------------------------------
__global__ void normalize_kernel(const float* __restrict__ x,
                                 const float* __restrict__ y) {
    int row = blockIdx.x;
    const float* src;
    __nv_bfloat16* dst;
    if (row < Nn) { src = x + (size_t)row * Dd; dst = g_xn + (size_t)row * Dd; }
    else { int r = row - Nn; src = y + (size_t)r * Dd; dst = g_yn + (size_t)r * Dd; }
    int t = threadIdx.x; // 0..63
    float4 v = reinterpret_cast<const float4*>(src)[t];
    float ss = v.x * v.x + v.y * v.y + v.z * v.z + v.w * v.w;
    #pragma unroll
    for (int off = 16; off > 0; off >>= 1)
        ss += __shfl_down_sync(0xffffffffu, ss, off);
    __shared__ float s[2];
    if ((t & 31) == 0) s[t >> 5] = ss;
    __syncthreads();
    float inv = 1.0f / fmaxf(sqrtf(s[0] + s[1]), 1e-8f);
    __nv_bfloat162 lo = __floats2bfloat162_rn(v.x * inv, v.y * inv);
    __nv_bfloat162 hi = __floats2bfloat162_rn(v.z * inv, v.w * inv);
    uint2 pk;
    pk.x = *reinterpret_cast<uint32_t*>(&lo);
    pk.y = *reinterpret_cast<uint32_t*>(&hi);
    reinterpret_cast<uint2*>(dst)[t] = pk;
}

// ---------------------------------------------------------------------------
// Async tile loader: 128 rows x 256 bf16 into 4 SW128 blocks. 512 thr x 8.
// ---------------------------------------------------------------------------
__device__ __forceinline__ void load_tile(const __nv_bfloat16* gbase, uint32_t sbase) {
    int tid = threadIdx.x;
    #pragma unroll
    for (int it = 0; it < 8; it++) {
        int idx = tid + it * NTHREADS;
        int r = idx >> 5;        // row
        int w = idx & 31;        // 16B granule within row (32 per row)
        int c = w >> 3;          // 128B block
        int g = w & 7;           // granule within block row
        const char* src = reinterpret_cast<const char*>(gbase + (size_t)r * Dd) + w * 16;
        uint32_t dst = sbase + c * BLOCK_BYTES + swz128(r * 128 + g * 16);
        cp_async16(dst, src);
    }
}

// ---------------------------------------------------------------------------
// Main fused kernel: mma.sync bf16 GEMM + branchless masked epilogue.
// Grid = ROW_TILES*COL_SPLITS = 128 CTAs, 512 threads (16 warps, 4M x 4N).
// Warp tile 32x32. Thread owns 4 rows x 8 cols of the 128x128 tile.
// ---------------------------------------------------------------------------
__global__ __launch_bounds__(NTHREADS)
void a2c_main(const int* __restrict__ labels,
              const int* __restrict__ labelsP,
              const int* __restrict__ realList,
              const int* __restrict__ isRealPtr,
              const float* __restrict__ att) {
    extern __shared__ __align__(1024) unsigned char smem[];
    const uint32_t sb = smem_u32(smem);
    const int tid = threadIdx.x;
    const int wid = tid >> 5;
    const int lane = tid & 31;
    const int warpM = wid & 3;        // 0..3 -> rows warpM*32..+31
    const int warpN = wid >> 2;       // 0..3 -> cols warpN*32..+31
    const int g   = lane >> 2;        // group id 0..7
    const int tig = lane & 3;         // thread-in-group

    const int rt = blockIdx.x >> 1;
    const int cspl = blockIdx.x & 1;
    const int rb = rt * TM;
    const int cb = cspl * COLS_PER_CTA;
    const bool useReal = (isRealPtr[0] != 0);

    int* sLp = reinterpret_cast<int*>(smem + SMEM_LP);

    // Prologue: A tile + B tile 0 async (one group), labels tile 0
    load_tile(g_xn + (size_t)rb * Dd, sb + SMEM_A);
    load_tile(g_yn + (size_t)cb * Dd, sb + SMEM_B0);
    CP_COMMIT();
    if (tid < TN) {
        int gc = cb + tid;
        int lp = labelsP[gc];
        if (useReal && realList[gc] == 0) lp = -1;
        sLp[tid] = lp;
    }

    // This thread's 4 row-slots: rs = mt*2+h -> row warpM*32 + mt*16 + h*8 + g
    int liOff4[4];
    int li4[4];
    #pragma unroll
    for (int rs = 0; rs < 4; rs++) {
        int rloc = warpM * 32 + (rs >> 1) * 16 + (rs & 1) * 8 + g;
        li4[rs] = labels[rb + rloc];
        liOff4[rs] = li4[rs] * Cc;
    }
    float rap[4] = {0.f, 0.f, 0.f, 0.f};
    float ran[4] = {0.f, 0.f, 0.f, 0.f};
    float rpc[4] = {0.f, 0.f, 0.f, 0.f};
    float rhc[4] = {0.f, 0.f, 0.f, 0.f};

    // ldmatrix lane addressing (constant parts)
    const int aRow = warpM * 32 + (lane & 15);        // + mt*16
    const int bNrow = warpN * 32 + (lane & 7) + ((lane >> 3) & 1) * 8;  // + p*16
    const int kHalf = (lane >> 4) * 16;               // +16B for k8-15 lanes

    for (int t = 0; t < NT; t++) {
        const int buf = t & 1;
        const uint32_t bsm = sb + (buf ? SMEM_B1 : SMEM_B0);

        // tile t's cp.async group is the only outstanding one
        CP_WAIT(0);
        __syncthreads();   // single barrier per tile: data ready + prev epilogue done

        // prefetch t+1 into the other buffer (overlaps compute below)
        if (t + 1 < NT) {
            const uint32_t nb = sb + ((t + 1) & 1 ? SMEM_B1 : SMEM_B0);
            load_tile(g_yn + (size_t)(cb + (t + 1) * TN) * Dd, nb);
            CP_COMMIT();
            if (tid < TN) {
                int gc = cb + (t + 1) * TN + tid;
                int lp = labelsP[gc];
                if (useReal && realList[gc] == 0) lp = -1;
                sLp[((t + 1) & 1) * TN + tid] = lp;
            }
        }

        // ---- compute this warp's 32x32 subtile: c[mt][nt][4] ----
        float c[2][4][4];
        #pragma unroll
        for (int mt = 0; mt < 2; mt++)
            #pragma unroll
            for (int nt = 0; nt < 4; nt++)
                #pragma unroll
                for (int e = 0; e < 4; e++)
                    c[mt][nt][e] = 0.f;

        #pragma unroll 4
        for (int ks = 0; ks < NUM_K_STEPS; ks++) {
            const int kb = ks * 32 + kHalf;
            uint32_t a[2][4];
            ldsm_x4(a[0], tile_addr(sb + SMEM_A, aRow, kb));
            ldsm_x4(a[1], tile_addr(sb + SMEM_A, aRow + 16, kb));
            uint32_t b[2][4];
            #pragma unroll
            for (int p = 0; p < 2; p++)
                ldsm_x4(b[p], tile_addr(bsm, bNrow + p * 16, kb));
            #pragma unroll
            for (int mt = 0; mt < 2; mt++)
                #pragma unroll
                for (int p = 0; p < 2; p++) {
                    mma_bf16(c[mt][2 * p],     a[mt], b[p][0], b[p][2]);
                    mma_bf16(c[mt][2 * p + 1], a[mt], b[p][1], b[p][3]);
                }
        }

        // ---- branchless epilogue: 8 batched att gathers per nt ----
        const int lpb = buf * TN;
        #pragma unroll
        for (int nt = 0; nt < 4; nt++) {
            const int col0 = warpN * 32 + nt * 8 + 2 * tig;
            const int lp0 = sLp[lpb + col0];
            const int lp1 = sLp[lpb + col0 + 1];
            const int clp0 = lp0 < 0 ? 0 : lp0;
            const int clp1 = lp1 < 0 ? 0 : lp1;
            // batch 8 independent gathers (MLP=8)
            float av[2][4];
            #pragma unroll
            for (int rs = 0; rs < 4; rs++) {
                av[0][rs] = __ldg(att + liOff4[rs] + clp0);
                av[1][rs] = __ldg(att + liOff4[rs] + clp1);
            }
            #pragma unroll
            for (int e = 0; e < 2; e++) {
                const int lp = e ? lp1 : lp0;
                const bool valid = (lp >= 0);
                #pragma unroll
                for (int mt = 0; mt < 2; mt++)
                    #pragma unroll
                    for (int h = 0; h < 2; h++) {
                        const int rs = mt * 2 + h;
                        const float d = 1.0f - c[mt][nt][h * 2 + e];
                        const float a = av[e][rs] * 0.5f + 0.4f;
                        const bool isPos = valid && (lp == li4[rs]);
                        const bool isHin = valid && (lp != li4[rs]) && (d < a);
                        rap[rs] += isPos ? fmaxf(d - 0.05f, 0.0f) : 0.0f;
                        rpc[rs] += isPos ? 1.0f : 0.0f;
                        ran[rs] += isHin ? (a - d) : 0.0f;
                        rhc[rs] += isHin ? 1.0f : 0.0f;
                    }
            }
        }
        // no trailing barrier: next iteration's prefetch targets the other
        // buffer/label half; the leading barrier orders buffer reuse at t+2.
    }

    // reduce over the 4 lanes sharing each row, then atomics (x4 warpN, x2 CTA)
    #pragma unroll
    for (int rs = 0; rs < 4; rs++) {
        float vap = rap[rs], van = ran[rs], vpc = rpc[rs], vhc = rhc[rs];
        #pragma unroll
        for (int off = 2; off > 0; off >>= 1) {
            vap += __shfl_down_sync(0xffffffffu, vap, off, 4);
            van += __shfl_down_sync(0xffffffffu, van, off, 4);
            vpc += __shfl_down_sync(0xffffffffu, vpc, off, 4);
            vhc += __shfl_down_sync(0xffffffffu, vhc, off, 4);
        }
        if (tig == 0) {
            int rglob = rb + warpM * 32 + (rs >> 1) * 16 + (rs & 1) * 8 + g;
            atomicAdd(&g_ap[rglob], vap);
            atomicAdd(&g_an[rglob], van);
            atomicAdd(&g_pc[rglob], vpc);
            atomicAdd(&g_hc[rglob], vhc);
        }
    }
}

// ---------------------------------------------------------------------------
// finalize: per-row loss, mean over rows. 32 blocks, atomicAdd into out
// (out zeroed by init_kernel).
// ---------------------------------------------------------------------------
__global__ void finalize_kernel(float* __restrict__ out) {
    __shared__ float s[8];
    const int rows_per_block = Nn / 32;                    // 256
    int r = blockIdx.x * rows_per_block + threadIdx.x;     // 256 threads
    float lap = g_ap[r] / (g_pc[r] + 1e-5f);
    float lan = g_an[r] / (g_hc[r] + 1e-5f);
    float acc = lap + lan;
    #pragma unroll
    for (int off = 16; off > 0; off >>= 1)
        acc += __shfl_down_sync(0xffffffffu, acc, off);
    if ((threadIdx.x & 31) == 0) s[threadIdx.x >> 5] = acc;
    __syncthreads();
    if (threadIdx.x == 0) {
        float b = 0.f;
        #pragma unroll
        for (int i = 0; i < 8; i++) b += s[i];
        atomicAdd(out, b * (1.0f / (float)Nn));
    }
}

// ---------------------------------------------------------------------------
// launch
// ---------------------------------------------------------------------------
extern "C" void kernel_launch(void* const* d_in, const int* in_sizes, int n_in,
                              void* d_out, int out_size) {
    const float* x       = (const float*)d_in[0];
    const int*   labels  = (const int*)d_in[1];
    const float* y       = (const float*)d_in[2];
    const int*   labelsP = (const int*)d_in[3];
    const int*   realL   = (const int*)d_in[6];
    const int*   isReal  = (const int*)d_in[7];
    const float* att     = (const float*)d_in[8];
    float* out = (float*)d_out;

    static bool attr_set = false;
    if (!attr_set) {
        cudaFuncSetAttribute(a2c_main, cudaFuncAttributeMaxDynamicSharedMemorySize,
                             SMEM_TOTAL);
        attr_set = true;
    }

    init_kernel<<<(Nn + 255) / 256, 256>>>(out);
    normalize_kernel<<<Nn + Pp, 64>>>(x, y);
    a2c_main<<<ROW_TILES * COL_SPLITS, NTHREADS, SMEM_TOTAL>>>(labels, labelsP, realL,
                                                               isReal, att);
    finalize_kernel<<<32, 256>>>(out);
}

// round 8
// speedup vs baseline: 1.5616x; 1.5616x over previous
#include <cuda_runtime.h>
#include <cuda_bf16.h>
#include <cstdint>

// ---------------------------------------------------------------------------
// Problem constants
// ---------------------------------------------------------------------------
static constexpr int Nn = 8192;
static constexpr int Pp = 8192;
static constexpr int Dd = 256;   // K
static constexpr int Cc = 1000;

// Tiling
static constexpr int TM = 128;
static constexpr int TN = 128;
static constexpr int COL_SPLITS = 2;
static constexpr int COLS_PER_CTA = Pp / COL_SPLITS;       // 4096
static constexpr int NT = COLS_PER_CTA / TN;               // 32
static constexpr int ROW_TILES = Nn / TM;                  // 64
static constexpr int NUM_K_STEPS = Dd / 16;                // 16

// SMEM layout
static constexpr int TILE_BYTES  = TM * Dd * 2;            // 65536
static constexpr int BLOCK_BYTES = 16384;
static constexpr int SMEM_A  = 0;
static constexpr int SMEM_B0 = SMEM_A + TILE_BYTES;
static constexpr int SMEM_B1 = SMEM_B0 + TILE_BYTES;
static constexpr int SMEM_LP = SMEM_B1 + TILE_BYTES;
static constexpr int SMEM_TOTAL = SMEM_LP + 2 * TN * 4;    // 197632

// ---------------------------------------------------------------------------
// Device scratch
// ---------------------------------------------------------------------------
__device__ __nv_bfloat16 g_xn[Nn * Dd];
__device__ __nv_bfloat16 g_yn[Pp * Dd];
__device__ float g_ap[Nn];
__device__ float g_an[Nn];
__device__ float g_pc[Nn];
__device__ float g_hc[Nn];
// label-sort scratch
__device__ int g_histx[1024];
__device__ int g_histy[1024];
__device__ int g_offx[1024];
__device__ int g_offy[1024];
__device__ int g_permx[Nn];
__device__ int g_permy[Pp];
__device__ int g_labx[Nn];
__device__ int g_laby[Pp];
__device__ int g_realy[Pp];

// ---------------------------------------------------------------------------
// PTX helpers (compute_100-safe)
// ---------------------------------------------------------------------------
__device__ __forceinline__ uint32_t smem_u32(const void* p) {
    uint32_t a;
    asm("{ .reg .u64 t; cvta.to.shared.u64 t, %1; cvt.u32.u64 %0, t; }" : "=r"(a) : "l"(p));
    return a;
}
__device__ __forceinline__ uint32_t swz128(uint32_t off) {
    return off ^ ((off >> 3) & 0x70);
}
__device__ __forceinline__ void cp_async16(uint32_t dst, const void* src) {
    asm volatile("cp.async.cg.shared.global [%0], [%1], 16;" :: "r"(dst), "l"(src));
}
#define CP_COMMIT()  asm volatile("cp.async.commit_group;" ::: "memory")
#define CP_WAIT(n)   asm volatile("cp.async.wait_group %0;" :: "n"(n) : "memory")

__device__ __forceinline__ void ldsm_x4(uint32_t* r, uint32_t addr) {
    asm volatile("ldmatrix.sync.aligned.m8n8.x4.shared.b16 {%0,%1,%2,%3}, [%4];"
                 : "=r"(r[0]), "=r"(r[1]), "=r"(r[2]), "=r"(r[3]) : "r"(addr));
}
__device__ __forceinline__ void mma_bf16(float* d, const uint32_t* a,
                                         uint32_t b0, uint32_t b1) {
    asm volatile(
        "mma.sync.aligned.m16n8k16.row.col.f32.bf16.bf16.f32 "
        "{%0,%1,%2,%3}, {%4,%5,%6,%7}, {%8,%9}, {%0,%1,%2,%3};"
        : "+f"(d[0]), "+f"(d[1]), "+f"(d[2]), "+f"(d[3])
        : "r"(a[0]), "r"(a[1]), "r"(a[2]), "r"(a[3]), "r"(b0), "r"(b1));
}
__device__ __forceinline__ uint32_t tile_addr(uint32_t base, int row, int kbyte) {
    return base + (kbyte >> 7) * BLOCK_BYTES + swz128(row * 128 + (kbyte & 127));
}

// ---------------------------------------------------------------------------
// init: zero accumulators + histograms + output
// ---------------------------------------------------------------------------
__global__ void init_kernel(float* __restrict__ out) {
    int i = blockIdx.x * blockDim.x + threadIdx.x;
    if (i < Nn) { g_ap[i] = 0.f; g_an[i] = 0.f; g_pc[i] = 0.f; g_hc[i] = 0.f; }
    if (i < 1024) { g_histx[i] = 0; g_histy[i] = 0; }
    if (i == 0) out[0] = 0.f;
}

// ---------------------------------------------------------------------------
// label histograms
// ---------------------------------------------------------------------------
__global__ void hist_kernel(const int* __restrict__ labels,
                            const int* __restrict__ labelsP) {
    int i = blockIdx.x * blockDim.x + threadIdx.x;
    if (i < Nn) atomicAdd(&g_histx[labels[i]], 1);
    if (i < Pp) atomicAdd(&g_histy[labelsP[i]], 1);
}

// ---------------------------------------------------------------------------
// exclusive scan over 1000 bins (1 block, 1024 threads, Hillis-Steele)
// ---------------------------------------------------------------------------
__global__ void scan_kernel() {
    __shared__ int sx[1024], sy[1024];
    int t = threadIdx.x;
    int hx = (t < Cc) ? g_histx[t] : 0;
    int hy = (t < Cc) ? g_histy[t] : 0;
    sx[t] = hx; sy[t] = hy;
    __syncthreads();
    #pragma unroll
    for (int off = 1; off < 1024; off <<= 1) {
        int vx = (t >= off) ? sx[t - off] : 0;
        int vy = (t >= off) ? sy[t - off] : 0;
        __syncthreads();
        sx[t] += vx; sy[t] += vy;
        __syncthreads();
    }
    if (t < Cc) {
        g_offx[t] = sx[t] - hx;
        g_offy[t] = sy[t] - hy;
    }
}

// ---------------------------------------------------------------------------
// scatter: build permutation + sorted labels / real mask
// ---------------------------------------------------------------------------
__global__ void scatter_kernel(const int* __restrict__ labels,
                               const int* __restrict__ labelsP,
                               const int* __restrict__ realL) {
    int i = blockIdx.x * blockDim.x + threadIdx.x;
    if (i < Nn) {
        int l = labels[i];
        int pos = atomicAdd(&g_offx[l], 1);
        g_permx[pos] = i;
        g_labx[pos] = l;
    }
    if (i < Pp) {
        int l = labelsP[i];
        int pos = atomicAdd(&g_offy[l], 1);
        g_permy[pos] = i;
        g_laby[pos] = l;
        g_realy[pos] = realL[i];
    }
}

// ---------------------------------------------------------------------------
// normalize rows (gathered through the sort permutation) -> bf16 scratch
// ---------------------------------------------------------------------------
__global__ void normalize_kernel(const float* __restrict__ x,
                                 const float* __restrict__ y) {
    int row = blockIdx.x;
    const float* src;
    __nv_bfloat16* dst;
    if (row < Nn) {
        src = x + (size_t)g_permx[row] * Dd;
        dst = g_xn + (size_t)row * Dd;
    } else {
        int r = row - Nn;
        src = y + (size_t)g_permy[r] * Dd;
        dst = g_yn + (size_t)r * Dd;
    }
    int t = threadIdx.x; // 0..63
    float4 v = reinterpret_cast<const float4*>(src)[t];
    float ss = v.x * v.x + v.y * v.y + v.z * v.z + v.w * v.w;
    #pragma unroll
    for (int off = 16; off > 0; off >>= 1)
        ss += __shfl_down_sync(0xffffffffu, ss, off);
    __shared__ float s[2];
    if ((t & 31) == 0) s[t >> 5] = ss;
    __syncthreads();
    float inv = 1.0f / fmaxf(sqrtf(s[0] + s[1]), 1e-8f);
    __nv_bfloat162 lo = __floats2bfloat162_rn(v.x * inv, v.y * inv);
    __nv_bfloat162 hi = __floats2bfloat162_rn(v.z * inv, v.w * inv);
    uint2 pk;
    pk.x = *reinterpret_cast<uint32_t*>(&lo);
    pk.y = *reinterpret_cast<uint32_t*>(&hi);
    reinterpret_cast<uint2*>(dst)[t] = pk;
}

// ---------------------------------------------------------------------------
// Async tile loader: 128 rows x 256 bf16 into 4 SW128 blocks. 256 thr x 16.
// ---------------------------------------------------------------------------
__device__ __forceinline__ void load_tile(const __nv_bfloat16* gbase, uint32_t sbase) {
    int tid = threadIdx.x;
    #pragma unroll
    for (int it = 0; it < 16; it++) {
        int idx = tid + it * 256;
        int r = idx >> 5;
        int w = idx & 31;
        int c = w >> 3;
        int g = w & 7;
        const char* src = reinterpret_cast<const char*>(gbase + (size_t)r * Dd) + w * 16;
        uint32_t dst = sbase + c * BLOCK_BYTES + swz128(r * 128 + g * 16);
        cp_async16(dst, src);
    }
}

// ---------------------------------------------------------------------------
// Main fused kernel (inputs are label-sorted).
// Grid = 128 CTAs, 256 threads (8 warps, 4M x 2N). Warp tile 32x64.
// ---------------------------------------------------------------------------
__global__ __launch_bounds__(256)
void a2c_main(const int* __restrict__ isRealPtr,
              const float* __restrict__ att) {
    extern __shared__ __align__(1024) unsigned char smem[];
    const uint32_t sb = smem_u32(smem);
    const int tid = threadIdx.x;
    const int wid = tid >> 5;
    const int lane = tid & 31;
    const int warpM = wid & 3;
    const int warpN = wid >> 2;
    const int g   = lane >> 2;
    const int tig = lane & 3;

    const int rt = blockIdx.x >> 1;
    const int cspl = blockIdx.x & 1;
    const int rb = rt * TM;
    const int cb = cspl * COLS_PER_CTA;
    const bool useReal = (isRealPtr[0] != 0);

    int* sLp = reinterpret_cast<int*>(smem + SMEM_LP);

    // Prologue: A tile + B tile 0 async, labels tile 0
    load_tile(g_xn + (size_t)rb * Dd, sb + SMEM_A);
    load_tile(g_yn + (size_t)cb * Dd, sb + SMEM_B0);
    CP_COMMIT();
    if (tid < TN) {
        int gc = cb + tid;
        int lp = g_laby[gc];
        if (useReal && g_realy[gc] == 0) lp = -1;
        sLp[tid] = lp;
    }

    int liOff4[4];
    int li4[4];
    #pragma unroll
    for (int rs = 0; rs < 4; rs++) {
        int rloc = warpM * 32 + (rs >> 1) * 16 + (rs & 1) * 8 + g;
        li4[rs] = g_labx[rb + rloc];
        liOff4[rs] = li4[rs] * Cc;
    }
    float rap[4] = {0.f, 0.f, 0.f, 0.f};
    float ran[4] = {0.f, 0.f, 0.f, 0.f};
    float rpc[4] = {0.f, 0.f, 0.f, 0.f};
    float rhc[4] = {0.f, 0.f, 0.f, 0.f};

    const int aRow = warpM * 32 + (lane & 15);
    const int bNrow = warpN * 64 + (lane & 7) + ((lane >> 3) & 1) * 8;
    const int kHalf = (lane >> 4) * 16;

    for (int t = 0; t < NT; t++) {
        const int buf = t & 1;
        const uint32_t bsm = sb + (buf ? SMEM_B1 : SMEM_B0);

        CP_WAIT(0);
        __syncthreads();

        if (t + 1 < NT) {
            const uint32_t nb = sb + ((t + 1) & 1 ? SMEM_B1 : SMEM_B0);
            load_tile(g_yn + (size_t)(cb + (t + 1) * TN) * Dd, nb);
            CP_COMMIT();
            if (tid < TN) {
                int gc = cb + (t + 1) * TN + tid;
                int lp = g_laby[gc];
                if (useReal && g_realy[gc] == 0) lp = -1;
                sLp[((t + 1) & 1) * TN + tid] = lp;
            }
        }

        // ---- compute 128x128 tile ----
        float c[2][8][4];
        #pragma unroll
        for (int mt = 0; mt < 2; mt++)
            #pragma unroll
            for (int nt = 0; nt < 8; nt++)
                #pragma unroll
                for (int e = 0; e < 4; e++)
                    c[mt][nt][e] = 0.f;

        #pragma unroll 4
        for (int ks = 0; ks < NUM_K_STEPS; ks++) {
            const int kb = ks * 32 + kHalf;
            uint32_t a[2][4];
            ldsm_x4(a[0], tile_addr(sb + SMEM_A, aRow, kb));
            ldsm_x4(a[1], tile_addr(sb + SMEM_A, aRow + 16, kb));
            uint32_t b[4][4];
            #pragma unroll
            for (int p = 0; p < 4; p++)
                ldsm_x4(b[p], tile_addr(bsm, bNrow + p * 16, kb));
            #pragma unroll
            for (int mt = 0; mt < 2; mt++)
                #pragma unroll
                for (int p = 0; p < 4; p++) {
                    mma_bf16(c[mt][2 * p],     a[mt], b[p][0], b[p][2]);
                    mma_bf16(c[mt][2 * p + 1], a[mt], b[p][1], b[p][3]);
                }
        }

        // ---- branchless epilogue (sorted labels -> L1-resident gathers) ----
        const int lpb = buf * TN;
        #pragma unroll
        for (int nt = 0; nt < 8; nt++) {
            const int col0 = warpN * 64 + nt * 8 + 2 * tig;
            const int lp0 = sLp[lpb + col0];
            const int lp1 = sLp[lpb + col0 + 1];
            const int clp0 = lp0 < 0 ? 0 : lp0;
            const int clp1 = lp1 < 0 ? 0 : lp1;
            float av[2][4];
            #pragma unroll
            for (int rs = 0; rs < 4; rs++) {
                av[0][rs] = __ldg(att + liOff4[rs] + clp0);
                av[1][rs] = __ldg(att + liOff4[rs] + clp1);
            }
            #pragma unroll
            for (int e = 0; e < 2; e++) {
                const int lp = e ? lp1 : lp0;
                const bool valid = (lp >= 0);
                #pragma unroll
                for (int mt = 0; mt < 2; mt++)
                    #pragma unroll
                    for (int h = 0; h < 2; h++) {
                        const int rs = mt * 2 + h;
                        const float d = 1.0f - c[mt][nt][h * 2 + e];
                        const float a = av[e][rs] * 0.5f + 0.4f;
                        const bool isPos = valid && (lp == li4[rs]);
                        const bool isHin = valid && (lp != li4[rs]) && (d < a);
                        rap[rs] += isPos ? fmaxf(d - 0.05f, 0.0f) : 0.0f;
                        rpc[rs] += isPos ? 1.0f : 0.0f;
                        ran[rs] += isHin ? (a - d) : 0.0f;
                        rhc[rs] += isHin ? 1.0f : 0.0f;
                    }
            }
        }
    }

    // reduce over the 4 lanes sharing each row, then atomics
    #pragma unroll
    for (int rs = 0; rs < 4; rs++) {
        float vap = rap[rs], van = ran[rs], vpc = rpc[rs], vhc = rhc[rs];
        #pragma unroll
        for (int off = 2; off > 0; off >>= 1) {
            vap += __shfl_down_sync(0xffffffffu, vap, off, 4);
            van += __shfl_down_sync(0xffffffffu, van, off, 4);
            vpc += __shfl_down_sync(0xffffffffu, vpc, off, 4);
            vhc += __shfl_down_sync(0xffffffffu, vhc, off, 4);
        }
        if (tig == 0) {
            int rglob = rb + warpM * 32 + (rs >> 1) * 16 + (rs & 1) * 8 + g;
            atomicAdd(&g_ap[rglob], vap);
            atomicAdd(&g_an[rglob], van);
            atomicAdd(&g_pc[rglob], vpc);
            atomicAdd(&g_hc[rglob], vhc);
        }
    }
}

// ---------------------------------------------------------------------------
// finalize: per-row loss, mean over rows (order-invariant under the sort).
// ---------------------------------------------------------------------------
__global__ void finalize_kernel(float* __restrict__ out) {
    __shared__ float s[8];
    const int rows_per_block = Nn / 32;
    int r = blockIdx.x * rows_per_block + threadIdx.x;
    float lap = g_ap[r] / (g_pc[r] + 1e-5f);
    float lan = g_an[r] / (g_hc[r] + 1e-5f);
    float acc = lap + lan;
    #pragma unroll
    for (int off = 16; off > 0; off >>= 1)
        acc += __shfl_down_sync(0xffffffffu, acc, off);
    if ((threadIdx.x & 31) == 0) s[threadIdx.x >> 5] = acc;
    __syncthreads();
    if (threadIdx.x == 0) {
        float b = 0.f;
        #pragma unroll
        for (int i = 0; i < 8; i++) b += s[i];
        atomicAdd(out, b * (1.0f / (float)Nn));
    }
}

// ---------------------------------------------------------------------------
// launch
// ---------------------------------------------------------------------------
extern "C" void kernel_launch(void* const* d_in, const int* in_sizes, int n_in,
                              void* d_out, int out_size) {
    const float* x       = (const float*)d_in[0];
    const int*   labels  = (const int*)d_in[1];
    const float* y       = (const float*)d_in[2];
    const int*   labelsP = (const int*)d_in[3];
    const int*   realL   = (const int*)d_in[6];
    const int*   isReal  = (const int*)d_in[7];
    const float* att     = (const float*)d_in[8];
    float* out = (float*)d_out;

    static bool attr_set = false;
    if (!attr_set) {
        cudaFuncSetAttribute(a2c_main, cudaFuncAttributeMaxDynamicSharedMemorySize,
                             SMEM_TOTAL);
        attr_set = true;
    }

    init_kernel<<<(Nn + 255) / 256, 256>>>(out);
    hist_kernel<<<(Nn + 255) / 256, 256>>>(labels, labelsP);
    scan_kernel<<<1, 1024>>>();
    scatter_kernel<<<(Nn + 255) / 256, 256>>>(labels, labelsP, realL);
    normalize_kernel<<<Nn + Pp, 64>>>(x, y);
    a2c_main<<<ROW_TILES * COL_SPLITS, 256, SMEM_TOTAL>>>(isReal, att);
    finalize_kernel<<<32, 256>>>(out);
}

// round 9
// speedup vs baseline: 1.5621x; 1.0003x over previous
#include <cuda_runtime.h>
#include <cuda_bf16.h>
#include <cstdint>

// ---------------------------------------------------------------------------
// Problem constants
// ---------------------------------------------------------------------------
static constexpr int Nn = 8192;
static constexpr int Pp = 8192;
static constexpr int Dd = 256;   // K
static constexpr int Cc = 1000;

// Tiling
static constexpr int TM = 128;
static constexpr int TN = 128;
static constexpr int COL_SPLITS = 2;
static constexpr int COLS_PER_CTA = Pp / COL_SPLITS;       // 4096
static constexpr int NT = COLS_PER_CTA / TN;               // 32
static constexpr int ROW_TILES = Nn / TM;                  // 64
static constexpr int NUM_K_STEPS = Dd / 16;                // 16

// SMEM layout
static constexpr int TILE_BYTES  = TM * Dd * 2;            // 65536
static constexpr int BLOCK_BYTES = 16384;
static constexpr int SMEM_A  = 0;
static constexpr int SMEM_B0 = SMEM_A + TILE_BYTES;
static constexpr int SMEM_B1 = SMEM_B0 + TILE_BYTES;
static constexpr int SMEM_LP = SMEM_B1 + TILE_BYTES;
static constexpr int SMEM_TOTAL = SMEM_LP + 2 * TN * 4;    // 197632

// ---------------------------------------------------------------------------
// Device scratch
// ---------------------------------------------------------------------------
__device__ __nv_bfloat16 g_xn[Nn * Dd];
__device__ __nv_bfloat16 g_yn[Pp * Dd];
__device__ float g_ap[Nn];
__device__ float g_an[Nn];
__device__ float g_pc[Nn];
__device__ float g_hc[Nn];
// label-sort scratch
__device__ int g_histx[1024];
__device__ int g_histy[1024];
__device__ int g_offx[1024];
__device__ int g_offy[1024];
__device__ int g_permx[Nn];
__device__ int g_permy[Pp];
__device__ int g_labx[Nn];
__device__ int g_laby[Pp];
__device__ int g_realy[Pp];

// ---------------------------------------------------------------------------
// PTX helpers (compute_100-safe)
// ---------------------------------------------------------------------------
__device__ __forceinline__ uint32_t smem_u32(const void* p) {
    uint32_t a;
    asm("{ .reg .u64 t; cvta.to.shared.u64 t, %1; cvt.u32.u64 %0, t; }" : "=r"(a) : "l"(p));
    return a;
}
__device__ __forceinline__ uint32_t swz128(uint32_t off) {
    return off ^ ((off >> 3) & 0x70);
}
__device__ __forceinline__ void cp_async16(uint32_t dst, const void* src) {
    asm volatile("cp.async.cg.shared.global [%0], [%1], 16;" :: "r"(dst), "l"(src));
}
#define CP_COMMIT()  asm volatile("cp.async.commit_group;" ::: "memory")
#define CP_WAIT(n)   asm volatile("cp.async.wait_group %0;" :: "n"(n) : "memory")

__device__ __forceinline__ void ldsm_x4(uint32_t* r, uint32_t addr) {
    asm volatile("ldmatrix.sync.aligned.m8n8.x4.shared.b16 {%0,%1,%2,%3}, [%4];"
                 : "=r"(r[0]), "=r"(r[1]), "=r"(r[2]), "=r"(r[3]) : "r"(addr));
}
__device__ __forceinline__ void mma_bf16(float* d, const uint32_t* a,
                                         uint32_t b0, uint32_t b1) {
    asm volatile(
        "mma.sync.aligned.m16n8k16.row.col.f32.bf16.bf16.f32 "
        "{%0,%1,%2,%3}, {%4,%5,%6,%7}, {%8,%9}, {%0,%1,%2,%3};"
        : "+f"(d[0]), "+f"(d[1]), "+f"(d[2]), "+f"(d[3])
        : "r"(a[0]), "r"(a[1]), "r"(a[2]), "r"(a[3]), "r"(b0), "r"(b1));
}
__device__ __forceinline__ uint32_t tile_addr(uint32_t base, int row, int kbyte) {
    return base + (kbyte >> 7) * BLOCK_BYTES + swz128(row * 128 + (kbyte & 127));
}

// ---------------------------------------------------------------------------
// init: zero accumulators + histograms + output
// ---------------------------------------------------------------------------
__global__ void init_kernel(float* __restrict__ out) {
    int i = blockIdx.x * blockDim.x + threadIdx.x;
    if (i < Nn) { g_ap[i] = 0.f; g_an[i] = 0.f; g_pc[i] = 0.f; g_hc[i] = 0.f; }
    if (i < 1024) { g_histx[i] = 0; g_histy[i] = 0; }
    if (i == 0) out[0] = 0.f;
}

// ---------------------------------------------------------------------------
// label histograms
// ---------------------------------------------------------------------------
__global__ void hist_kernel(const int* __restrict__ labels,
                            const int* __restrict__ labelsP) {
    int i = blockIdx.x * blockDim.x + threadIdx.x;
    if (i < Nn) atomicAdd(&g_histx[labels[i]], 1);
    if (i < Pp) atomicAdd(&g_histy[labelsP[i]], 1);
}

// ---------------------------------------------------------------------------
// exclusive scan over 1000 bins (1 block, 1024 threads, Hillis-Steele)
// ---------------------------------------------------------------------------
__global__ void scan_kernel() {
    __shared__ int sx[1024], sy[1024];
    int t = threadIdx.x;
    int hx = (t < Cc) ? g_histx[t] : 0;
    int hy = (t < Cc) ? g_histy[t] : 0;
    sx[t] = hx; sy[t] = hy;
    __syncthreads();
    #pragma unroll
    for (int off = 1; off < 1024; off <<= 1) {
        int vx = (t >= off) ? sx[t - off] : 0;
        int vy = (t >= off) ? sy[t - off] : 0;
        __syncthreads();
        sx[t] += vx; sy[t] += vy;
        __syncthreads();
    }
    if (t < Cc) {
        g_offx[t] = sx[t] - hx;
        g_offy[t] = sy[t] - hy;
    }
}

// ---------------------------------------------------------------------------
// scatter: build permutation + sorted labels / real mask
// ---------------------------------------------------------------------------
__global__ void scatter_kernel(const int* __restrict__ labels,
                               const int* __restrict__ labelsP,
                               const int* __restrict__ realL) {
    int i = blockIdx.x * blockDim.x + threadIdx.x;
    if (i < Nn) {
        int l = labels[i];
        int pos = atomicAdd(&g_offx[l], 1);
        g_permx[pos] = i;
        g_labx[pos] = l;
    }
    if (i < Pp) {
        int l = labelsP[i];
        int pos = atomicAdd(&g_offy[l], 1);
        g_permy[pos] = i;
        g_laby[pos] = l;
        g_realy[pos] = realL[i];
    }
}

// ---------------------------------------------------------------------------
// normalize rows (gathered through the sort permutation) -> bf16 scratch
// ---------------------------------------------------------------------------
__global__ void normalize_kernel(const float* __restrict__ x,
                                 const float* __restrict__ y) {
    int row = blockIdx.x;
    const float* src;
    __nv_bfloat16* dst;
    if (row < Nn) {
        src = x + (size_t)g_permx[row] * Dd;
        dst = g_xn + (size_t)row * Dd;
    } else {
        int r = row - Nn;
        src = y + (size_t)g_permy[r] * Dd;
        dst = g_yn + (size_t)r * Dd;
    }
    int t = threadIdx.x; // 0..63
    float4 v = reinterpret_cast<const float4*>(src)[t];
    float ss = v.x * v.x + v.y * v.y + v.z * v.z + v.w * v.w;
    #pragma unroll
    for (int off = 16; off > 0; off >>= 1)
        ss += __shfl_down_sync(0xffffffffu, ss, off);
    __shared__ float s[2];
    if ((t & 31) == 0) s[t >> 5] = ss;
    __syncthreads();
    float inv = 1.0f / fmaxf(sqrtf(s[0] + s[1]), 1e-8f);
    __nv_bfloat162 lo = __floats2bfloat162_rn(v.x * inv, v.y * inv);
    __nv_bfloat162 hi = __floats2bfloat162_rn(v.z * inv, v.w * inv);
    uint2 pk;
    pk.x = *reinterpret_cast<uint32_t*>(&lo);
    pk.y = *reinterpret_cast<uint32_t*>(&hi);
    reinterpret_cast<uint2*>(dst)[t] = pk;
}

// ---------------------------------------------------------------------------
// Async tile loader: 128 rows x 256 bf16 into 4 SW128 blocks. 256 thr x 16.
// ---------------------------------------------------------------------------
__device__ __forceinline__ void load_tile(const __nv_bfloat16* gbase, uint32_t sbase) {
    int tid = threadIdx.x;
    #pragma unroll
    for (int it = 0; it < 16; it++) {
        int idx = tid + it * 256;
        int r = idx >> 5;
        int w = idx & 31;
        int c = w >> 3;
        int g = w & 7;
        const char* src = reinterpret_cast<const char*>(gbase + (size_t)r * Dd) + w * 16;
        uint32_t dst = sbase + c * BLOCK_BYTES + swz128(r * 128 + g * 16);
        cp_async16(dst, src);
    }
}

// ---------------------------------------------------------------------------
// Main fused kernel (inputs label-sorted; A fragments register-resident).
// Grid = 128 CTAs, 256 threads (8 warps, 4M x 2N). Warp tile 32x64.
// ---------------------------------------------------------------------------
__global__ __launch_bounds__(256)
void a2c_main(const int* __restrict__ isRealPtr,
              const float* __restrict__ att) {
    extern __shared__ __align__(1024) unsigned char smem[];
    const uint32_t sb = smem_u32(smem);
    const int tid = threadIdx.x;
    const int wid = tid >> 5;
    const int lane = tid & 31;
    const int warpM = wid & 3;
    const int warpN = wid >> 2;
    const int g   = lane >> 2;
    const int tig = lane & 3;

    const int rt = blockIdx.x >> 1;
    const int cspl = blockIdx.x & 1;
    const int rb = rt * TM;
    const int cb = cspl * COLS_PER_CTA;
    const bool useReal = (isRealPtr[0] != 0);

    int* sLp = reinterpret_cast<int*>(smem + SMEM_LP);

    // Prologue: A tile + B tile 0 async (one group), labels tile 0
    load_tile(g_xn + (size_t)rb * Dd, sb + SMEM_A);
    load_tile(g_yn + (size_t)cb * Dd, sb + SMEM_B0);
    CP_COMMIT();
    if (tid < TN) {
        int gc = cb + tid;
        int lp = g_laby[gc];
        if (useReal && g_realy[gc] == 0) lp = -1;
        sLp[tid] = lp;
    }

    int liOff4[4];
    int li4[4];
    #pragma unroll
    for (int rs = 0; rs < 4; rs++) {
        int rloc = warpM * 32 + (rs >> 1) * 16 + (rs & 1) * 8 + g;
        li4[rs] = g_labx[rb + rloc];
        liOff4[rs] = li4[rs] * Cc;
    }
    float rap[4] = {0.f, 0.f, 0.f, 0.f};
    float ran[4] = {0.f, 0.f, 0.f, 0.f};
    float rpc[4] = {0.f, 0.f, 0.f, 0.f};
    float rhc[4] = {0.f, 0.f, 0.f, 0.f};

    const int aRow = warpM * 32 + (lane & 15);
    const int bNrow = warpN * 64 + (lane & 7) + ((lane >> 3) & 1) * 8;
    const int kHalf = (lane >> 4) * 16;

    // ---- A fragments -> registers, once for all 32 B tiles ----
    CP_WAIT(0);           // A + B0 complete
    __syncthreads();
    uint32_t af[NUM_K_STEPS][2][4];
    #pragma unroll
    for (int ks = 0; ks < NUM_K_STEPS; ks++) {
        const int kb = ks * 32 + kHalf;
        ldsm_x4(af[ks][0], tile_addr(sb + SMEM_A, aRow, kb));
        ldsm_x4(af[ks][1], tile_addr(sb + SMEM_A, aRow + 16, kb));
    }

    for (int t = 0; t < NT; t++) {
        const int buf = t & 1;
        const uint32_t bsm = sb + (buf ? SMEM_B1 : SMEM_B0);

        CP_WAIT(0);
        __syncthreads();   // tile t data ready + prev epilogue done

        // prefetch t+1 (overlaps compute below)
        if (t + 1 < NT) {
            const uint32_t nb = sb + ((t + 1) & 1 ? SMEM_B1 : SMEM_B0);
            load_tile(g_yn + (size_t)(cb + (t + 1) * TN) * Dd, nb);
            CP_COMMIT();
            if (tid < TN) {
                int gc = cb + (t + 1) * TN + tid;
                int lp = g_laby[gc];
                if (useReal && g_realy[gc] == 0) lp = -1;
                sLp[((t + 1) & 1) * TN + tid] = lp;
            }
        }

        // ---- compute 128x128 tile: B from smem, A from registers ----
        float c[2][8][4];
        #pragma unroll
        for (int mt = 0; mt < 2; mt++)
            #pragma unroll
            for (int nt = 0; nt < 8; nt++)
                #pragma unroll
                for (int e = 0; e < 4; e++)
                    c[mt][nt][e] = 0.f;

        #pragma unroll
        for (int ks = 0; ks < NUM_K_STEPS; ks++) {
            const int kb = ks * 32 + kHalf;
            uint32_t b[4][4];
            #pragma unroll
            for (int p = 0; p < 4; p++)
                ldsm_x4(b[p], tile_addr(bsm, bNrow + p * 16, kb));
            #pragma unroll
            for (int mt = 0; mt < 2; mt++)
                #pragma unroll
                for (int p = 0; p < 4; p++) {
                    mma_bf16(c[mt][2 * p],     af[ks][mt], b[p][0], b[p][2]);
                    mma_bf16(c[mt][2 * p + 1], af[ks][mt], b[p][1], b[p][3]);
                }
        }

        // ---- branchless epilogue (sorted labels -> L1-resident gathers) ----
        const int lpb = buf * TN;
        #pragma unroll
        for (int nt = 0; nt < 8; nt++) {
            const int col0 = warpN * 64 + nt * 8 + 2 * tig;
            const int lp0 = sLp[lpb + col0];
            const int lp1 = sLp[lpb + col0 + 1];
            const int clp0 = lp0 < 0 ? 0 : lp0;
            const int clp1 = lp1 < 0 ? 0 : lp1;
            float av[2][4];
            #pragma unroll
            for (int rs = 0; rs < 4; rs++) {
                av[0][rs] = __ldg(att + liOff4[rs] + clp0);
                av[1][rs] = __ldg(att + liOff4[rs] + clp1);
            }
            #pragma unroll
            for (int e = 0; e < 2; e++) {
                const int lp = e ? lp1 : lp0;
                const bool valid = (lp >= 0);
                #pragma unroll
                for (int mt = 0; mt < 2; mt++)
                    #pragma unroll
                    for (int h = 0; h < 2; h++) {
                        const int rs = mt * 2 + h;
                        const float d = 1.0f - c[mt][nt][h * 2 + e];
                        const float a = av[e][rs] * 0.5f + 0.4f;
                        const bool isPos = valid && (lp == li4[rs]);
                        const bool isHin = valid && (lp != li4[rs]) && (d < a);
                        rap[rs] += isPos ? fmaxf(d - 0.05f, 0.0f) : 0.0f;
                        rpc[rs] += isPos ? 1.0f : 0.0f;
                        ran[rs] += isHin ? (a - d) : 0.0f;
                        rhc[rs] += isHin ? 1.0f : 0.0f;
                    }
            }
        }
    }

    // reduce over the 4 lanes sharing each row, then atomics
    #pragma unroll
    for (int rs = 0; rs < 4; rs++) {
        float vap = rap[rs], van = ran[rs], vpc = rpc[rs], vhc = rhc[rs];
        #pragma unroll
        for (int off = 2; off > 0; off >>= 1) {
            vap += __shfl_down_sync(0xffffffffu, vap, off, 4);
            van += __shfl_down_sync(0xffffffffu, van, off, 4);
            vpc += __shfl_down_sync(0xffffffffu, vpc, off, 4);
            vhc += __shfl_down_sync(0xffffffffu, vhc, off, 4);
        }
        if (tig == 0) {
            int rglob = rb + warpM * 32 + (rs >> 1) * 16 + (rs & 1) * 8 + g;
            atomicAdd(&g_ap[rglob], vap);
            atomicAdd(&g_an[rglob], van);
            atomicAdd(&g_pc[rglob], vpc);
            atomicAdd(&g_hc[rglob], vhc);
        }
    }
}

// ---------------------------------------------------------------------------
// finalize: per-row loss, mean over rows (order-invariant under the sort).
// ---------------------------------------------------------------------------
__global__ void finalize_kernel(float* __restrict__ out) {
    __shared__ float s[8];
    const int rows_per_block = Nn / 32;
    int r = blockIdx.x * rows_per_block + threadIdx.x;
    float lap = g_ap[r] / (g_pc[r] + 1e-5f);
    float lan = g_an[r] / (g_hc[r] + 1e-5f);
    float acc = lap + lan;
    #pragma unroll
    for (int off = 16; off > 0; off >>= 1)
        acc += __shfl_down_sync(0xffffffffu, acc, off);
    if ((threadIdx.x & 31) == 0) s[threadIdx.x >> 5] = acc;
    __syncthreads();
    if (threadIdx.x == 0) {
        float b = 0.f;
        #pragma unroll
        for (int i = 0; i < 8; i++) b += s[i];
        atomicAdd(out, b * (1.0f / (float)Nn));
    }
}

// ---------------------------------------------------------------------------
// launch
// ---------------------------------------------------------------------------
extern "C" void kernel_launch(void* const* d_in, const int* in_sizes, int n_in,
                              void* d_out, int out_size) {
    const float* x       = (const float*)d_in[0];
    const int*   labels  = (const int*)d_in[1];
    const float* y       = (const float*)d_in[2];
    const int*   labelsP = (const int*)d_in[3];
    const int*   realL   = (const int*)d_in[6];
    const int*   isReal  = (const int*)d_in[7];
    const float* att     = (const float*)d_in[8];
    float* out = (float*)d_out;

    static bool attr_set = false;
    if (!attr_set) {
        cudaFuncSetAttribute(a2c_main, cudaFuncAttributeMaxDynamicSharedMemorySize,
                             SMEM_TOTAL);
        attr_set = true;
    }

    init_kernel<<<(Nn + 255) / 256, 256>>>(out);
    hist_kernel<<<(Nn + 255) / 256, 256>>>(labels, labelsP);
    scan_kernel<<<1, 1024>>>();
    scatter_kernel<<<(Nn + 255) / 256, 256>>>(labels, labelsP, realL);
    normalize_kernel<<<Nn + Pp, 64>>>(x, y);
    a2c_main<<<ROW_TILES * COL_SPLITS, 256, SMEM_TOTAL>>>(isReal, att);
    finalize_kernel<<<32, 256>>>(out);
}

// round 10
// speedup vs baseline: 1.5762x; 1.0090x over previous
#include <cuda_runtime.h>
#include <cuda_bf16.h>
#include <cstdint>

// ---------------------------------------------------------------------------
// Problem constants
// ---------------------------------------------------------------------------
static constexpr int Nn = 8192;
static constexpr int Pp = 8192;
static constexpr int Dd = 256;   // K
static constexpr int Cc = 1000;

// Tiling
static constexpr int TM = 128;
static constexpr int TN = 128;
static constexpr int COL_SPLITS = 2;
static constexpr int COLS_PER_CTA = Pp / COL_SPLITS;       // 4096
static constexpr int NT = COLS_PER_CTA / TN;               // 32
static constexpr int ROW_TILES = Nn / TM;                  // 64
static constexpr int NUM_K_STEPS = Dd / 32;                // 8 (32 e4m3 per mma)

// SMEM: tiles are 128 rows x 256 B (fp8), stored as 2 blocks of
// [128 rows x 128B], SW128-swizzled within each block.
static constexpr int TILE_BYTES  = TM * Dd;                // 32768
static constexpr int BLOCK_BYTES = 16384;
static constexpr int SMEM_A  = 0;
static constexpr int SMEM_B0 = SMEM_A + TILE_BYTES;        // 32768
static constexpr int SMEM_B1 = SMEM_B0 + TILE_BYTES;       // 65536
static constexpr int SMEM_LP = SMEM_B1 + TILE_BYTES;       // 98304
static constexpr int SMEM_TOTAL = SMEM_LP + 2 * TN * 4;    // 99328

// ---------------------------------------------------------------------------
// Device scratch
// ---------------------------------------------------------------------------
__device__ uint8_t g_x8[Nn * Dd];   // e4m3 normalized instances (sorted order)
__device__ uint8_t g_y8[Pp * Dd];   // e4m3 normalized proxies  (sorted order)
__device__ float g_ap[Nn];
__device__ float g_an[Nn];
__device__ float g_pc[Nn];
__device__ float g_hc[Nn];
// label-sort scratch
__device__ int g_histx[1024];
__device__ int g_histy[1024];
__device__ int g_offx[1024];
__device__ int g_offy[1024];
__device__ int g_permx[Nn];
__device__ int g_permy[Pp];
__device__ int g_labx[Nn];
__device__ int g_laby[Pp];
__device__ int g_realy[Pp];

// ---------------------------------------------------------------------------
// PTX helpers (compute_100-safe)
// ---------------------------------------------------------------------------
__device__ __forceinline__ uint32_t smem_u32(const void* p) {
    uint32_t a;
    asm("{ .reg .u64 t; cvta.to.shared.u64 t, %1; cvt.u32.u64 %0, t; }" : "=r"(a) : "l"(p));
    return a;
}
__device__ __forceinline__ uint32_t swz128(uint32_t off) {
    return off ^ ((off >> 3) & 0x70);
}
__device__ __forceinline__ void cp_async16(uint32_t dst, const void* src) {
    asm volatile("cp.async.cg.shared.global [%0], [%1], 16;" :: "r"(dst), "l"(src));
}
#define CP_COMMIT()  asm volatile("cp.async.commit_group;" ::: "memory")
#define CP_WAIT(n)   asm volatile("cp.async.wait_group %0;" :: "n"(n) : "memory")

__device__ __forceinline__ void ldsm_x4(uint32_t* r, uint32_t addr) {
    asm volatile("ldmatrix.sync.aligned.m8n8.x4.shared.b16 {%0,%1,%2,%3}, [%4];"
                 : "=r"(r[0]), "=r"(r[1]), "=r"(r[2]), "=r"(r[3]) : "r"(addr));
}
// FP8 e4m3 MMA: m16n8k32, fp32 accumulate. Fragments are byte-identical to
// the bf16 m16n8k16 layout, so the same ldmatrix addressing applies.
__device__ __forceinline__ void mma_fp8(float* d, const uint32_t* a,
                                        uint32_t b0, uint32_t b1) {
    asm volatile(
        "mma.sync.aligned.m16n8k32.row.col.f32.e4m3.e4m3.f32 "
        "{%0,%1,%2,%3}, {%4,%5,%6,%7}, {%8,%9}, {%0,%1,%2,%3};"
        : "+f"(d[0]), "+f"(d[1]), "+f"(d[2]), "+f"(d[3])
        : "r"(a[0]), "r"(a[1]), "r"(a[2]), "r"(a[3]), "r"(b0), "r"(b1));
}
// tile element address: (row, kbyte) with kbyte in [0,256)
__device__ __forceinline__ uint32_t tile_addr(uint32_t base, int row, int kbyte) {
    return base + (kbyte >> 7) * BLOCK_BYTES + swz128(row * 128 + (kbyte & 127));
}
// pack 4 floats -> 4 e4m3 bytes (elements in ascending order, little-endian)
__device__ __forceinline__ uint32_t pack_e4m3x4(float f0, float f1, float f2, float f3) {
    uint16_t lo, hi;
    asm("cvt.rn.satfinite.e4m3x2.f32 %0, %1, %2;" : "=h"(lo) : "f"(f1), "f"(f0));
    asm("cvt.rn.satfinite.e4m3x2.f32 %0, %1, %2;" : "=h"(hi) : "f"(f3), "f"(f2));
    return (uint32_t)lo | ((uint32_t)hi << 16);
}

// ---------------------------------------------------------------------------
// init: zero accumulators + histograms + output
// ---------------------------------------------------------------------------
__global__ void init_kernel(float* __restrict__ out) {
    int i = blockIdx.x * blockDim.x + threadIdx.x;
    if (i < Nn) { g_ap[i] = 0.f; g_an[i] = 0.f; g_pc[i] = 0.f; g_hc[i] = 0.f; }
    if (i < 1024) { g_histx[i] = 0; g_histy[i] = 0; }
    if (i == 0) out[0] = 0.f;
}

// ---------------------------------------------------------------------------
// label histograms
// ---------------------------------------------------------------------------
__global__ void hist_kernel(const int* __restrict__ labels,
                            const int* __restrict__ labelsP) {
    int i = blockIdx.x * blockDim.x + threadIdx.x;
    if (i < Nn) atomicAdd(&g_histx[labels[i]], 1);
    if (i < Pp) atomicAdd(&g_histy[labelsP[i]], 1);
}

// ---------------------------------------------------------------------------
// exclusive scan over 1000 bins (1 block, 1024 threads, Hillis-Steele)
// ---------------------------------------------------------------------------
__global__ void scan_kernel() {
    __shared__ int sx[1024], sy[1024];
    int t = threadIdx.x;
    int hx = (t < Cc) ? g_histx[t] : 0;
    int hy = (t < Cc) ? g_histy[t] : 0;
    sx[t] = hx; sy[t] = hy;
    __syncthreads();
    #pragma unroll
    for (int off = 1; off < 1024; off <<= 1) {
        int vx = (t >= off) ? sx[t - off] : 0;
        int vy = (t >= off) ? sy[t - off] : 0;
        __syncthreads();
        sx[t] += vx; sy[t] += vy;
        __syncthreads();
    }
    if (t < Cc) {
        g_offx[t] = sx[t] - hx;
        g_offy[t] = sy[t] - hy;
    }
}

// ---------------------------------------------------------------------------
// scatter: build permutation + sorted labels / real mask
// ---------------------------------------------------------------------------
__global__ void scatter_kernel(const int* __restrict__ labels,
                               const int* __restrict__ labelsP,
                               const int* __restrict__ realL) {
    int i = blockIdx.x * blockDim.x + threadIdx.x;
    if (i < Nn) {
        int l = labels[i];
        int pos = atomicAdd(&g_offx[l], 1);
        g_permx[pos] = i;
        g_labx[pos] = l;
    }
    if (i < Pp) {
        int l = labelsP[i];
        int pos = atomicAdd(&g_offy[l], 1);
        g_permy[pos] = i;
        g_laby[pos] = l;
        g_realy[pos] = realL[i];
    }
}

// ---------------------------------------------------------------------------
// normalize rows (gathered through the sort permutation) -> e4m3 scratch
// ---------------------------------------------------------------------------
__global__ void normalize_kernel(const float* __restrict__ x,
                                 const float* __restrict__ y) {
    int row = blockIdx.x;
    const float* src;
    uint8_t* dst;
    if (row < Nn) {
        src = x + (size_t)g_permx[row] * Dd;
        dst = g_x8 + (size_t)row * Dd;
    } else {
        int r = row - Nn;
        src = y + (size_t)g_permy[r] * Dd;
        dst = g_y8 + (size_t)r * Dd;
    }
    int t = threadIdx.x; // 0..63
    float4 v = reinterpret_cast<const float4*>(src)[t];
    float ss = v.x * v.x + v.y * v.y + v.z * v.z + v.w * v.w;
    #pragma unroll
    for (int off = 16; off > 0; off >>= 1)
        ss += __shfl_down_sync(0xffffffffu, ss, off);
    __shared__ float s[2];
    if ((t & 31) == 0) s[t >> 5] = ss;
    __syncthreads();
    float inv = 1.0f / fmaxf(sqrtf(s[0] + s[1]), 1e-8f);
    uint32_t pk = pack_e4m3x4(v.x * inv, v.y * inv, v.z * inv, v.w * inv);
    reinterpret_cast<uint32_t*>(dst)[t] = pk;
}

// ---------------------------------------------------------------------------
// Async tile loader: 128 rows x 256 B (fp8) into 2 SW128 blocks. 256 thr x 8.
// ---------------------------------------------------------------------------
__device__ __forceinline__ void load_tile(const uint8_t* gbase, uint32_t sbase) {
    int tid = threadIdx.x;
    #pragma unroll
    for (int it = 0; it < 8; it++) {
        int idx = tid + it * 256;
        int r = idx >> 4;        // row (16 granules of 16B per row)
        int w = idx & 15;        // granule within row
        int c = w >> 3;          // 128B block
        int g = w & 7;           // granule within block row
        const uint8_t* src = gbase + (size_t)r * Dd + w * 16;
        uint32_t dst = sbase + c * BLOCK_BYTES + swz128(r * 128 + g * 16);
        cp_async16(dst, src);
    }
}

// ---------------------------------------------------------------------------
// Main fused kernel: FP8 QMMA GEMM + branchless masked epilogue.
// Grid = 128 CTAs, 256 threads (8 warps, 4M x 2N). Warp tile 32x64.
// ---------------------------------------------------------------------------
__global__ __launch_bounds__(256)
void a2c_main(const int* __restrict__ isRealPtr,
              const float* __restrict__ att) {
    extern __shared__ __align__(1024) unsigned char smem[];
    const uint32_t sb = smem_u32(smem);
    const int tid = threadIdx.x;
    const int wid = tid >> 5;
    const int lane = tid & 31;
    const int warpM = wid & 3;
    const int warpN = wid >> 2;
    const int g   = lane >> 2;
    const int tig = lane & 3;

    const int rt = blockIdx.x >> 1;
    const int cspl = blockIdx.x & 1;
    const int rb = rt * TM;
    const int cb = cspl * COLS_PER_CTA;
    const bool useReal = (isRealPtr[0] != 0);

    int* sLp = reinterpret_cast<int*>(smem + SMEM_LP);

    // Prologue: A tile + B tile 0 async (one group), labels tile 0
    load_tile(g_x8 + (size_t)rb * Dd, sb + SMEM_A);
    load_tile(g_y8 + (size_t)cb * Dd, sb + SMEM_B0);
    CP_COMMIT();
    if (tid < TN) {
        int gc = cb + tid;
        int lp = g_laby[gc];
        if (useReal && g_realy[gc] == 0) lp = -1;
        sLp[tid] = lp;
    }

    int liOff4[4];
    int li4[4];
    #pragma unroll
    for (int rs = 0; rs < 4; rs++) {
        int rloc = warpM * 32 + (rs >> 1) * 16 + (rs & 1) * 8 + g;
        li4[rs] = g_labx[rb + rloc];
        liOff4[rs] = li4[rs] * Cc;
    }
    float rap[4] = {0.f, 0.f, 0.f, 0.f};
    float ran[4] = {0.f, 0.f, 0.f, 0.f};
    float rpc[4] = {0.f, 0.f, 0.f, 0.f};
    float rhc[4] = {0.f, 0.f, 0.f, 0.f};

    const int aRow = warpM * 32 + (lane & 15);
    const int bNrow = warpN * 64 + (lane & 7) + ((lane >> 3) & 1) * 8;
    const int kHalf = (lane >> 4) * 16;      // 16-byte half within 32B k-step

    // ---- A fragments -> registers, once for all 32 B tiles ----
    CP_WAIT(0);           // A + B0 complete
    __syncthreads();
    uint32_t af[NUM_K_STEPS][2][4];
    #pragma unroll
    for (int ks = 0; ks < NUM_K_STEPS; ks++) {
        const int kb = ks * 32 + kHalf;
        ldsm_x4(af[ks][0], tile_addr(sb + SMEM_A, aRow, kb));
        ldsm_x4(af[ks][1], tile_addr(sb + SMEM_A, aRow + 16, kb));
    }

    for (int t = 0; t < NT; t++) {
        const int buf = t & 1;
        const uint32_t bsm = sb + (buf ? SMEM_B1 : SMEM_B0);

        CP_WAIT(0);
        __syncthreads();   // tile t data ready + prev epilogue done

        // prefetch t+1 (overlaps compute below)
        if (t + 1 < NT) {
            const uint32_t nb = sb + ((t + 1) & 1 ? SMEM_B1 : SMEM_B0);
            load_tile(g_y8 + (size_t)(cb + (t + 1) * TN) * Dd, nb);
            CP_COMMIT();
            if (tid < TN) {
                int gc = cb + (t + 1) * TN + tid;
                int lp = g_laby[gc];
                if (useReal && g_realy[gc] == 0) lp = -1;
                sLp[((t + 1) & 1) * TN + tid] = lp;
            }
        }

        // ---- compute 128x128 tile: B from smem, A from registers ----
        float c[2][8][4];
        #pragma unroll
        for (int mt = 0; mt < 2; mt++)
            #pragma unroll
            for (int nt = 0; nt < 8; nt++)
                #pragma unroll
                for (int e = 0; e < 4; e++)
                    c[mt][nt][e] = 0.f;

        #pragma unroll
        for (int ks = 0; ks < NUM_K_STEPS; ks++) {
            const int kb = ks * 32 + kHalf;
            uint32_t b[4][4];
            #pragma unroll
            for (int p = 0; p < 4; p++)
                ldsm_x4(b[p], tile_addr(bsm, bNrow + p * 16, kb));
            #pragma unroll
            for (int mt = 0; mt < 2; mt++)
                #pragma unroll
                for (int p = 0; p < 4; p++) {
                    mma_fp8(c[mt][2 * p],     af[ks][mt], b[p][0], b[p][2]);
                    mma_fp8(c[mt][2 * p + 1], af[ks][mt], b[p][1], b[p][3]);
                }
        }

        // ---- branchless epilogue (sorted labels -> L1-resident gathers) ----
        const int lpb = buf * TN;
        #pragma unroll
        for (int nt = 0; nt < 8; nt++) {
            const int col0 = warpN * 64 + nt * 8 + 2 * tig;
            const int lp0 = sLp[lpb + col0];
            const int lp1 = sLp[lpb + col0 + 1];
            const int clp0 = lp0 < 0 ? 0 : lp0;
            const int clp1 = lp1 < 0 ? 0 : lp1;
            float av[2][4];
            #pragma unroll
            for (int rs = 0; rs < 4; rs++) {
                av[0][rs] = __ldg(att + liOff4[rs] + clp0);
                av[1][rs] = __ldg(att + liOff4[rs] + clp1);
            }
            #pragma unroll
            for (int e = 0; e < 2; e++) {
                const int lp = e ? lp1 : lp0;
                const bool valid = (lp >= 0);
                #pragma unroll
                for (int mt = 0; mt < 2; mt++)
                    #pragma unroll
                    for (int h = 0; h < 2; h++) {
                        const int rs = mt * 2 + h;
                        const float d = 1.0f - c[mt][nt][h * 2 + e];
                        const float a = av[e][rs] * 0.5f + 0.4f;
                        const bool isPos = valid && (lp == li4[rs]);
                        const bool isHin = valid && (lp != li4[rs]) && (d < a);
                        rap[rs] += isPos ? fmaxf(d - 0.05f, 0.0f) : 0.0f;
                        rpc[rs] += isPos ? 1.0f : 0.0f;
                        ran[rs] += isHin ? (a - d) : 0.0f;
                        rhc[rs] += isHin ? 1.0f : 0.0f;
                    }
            }
        }
    }

    // reduce over the 4 lanes sharing each row, then atomics
    #pragma unroll
    for (int rs = 0; rs < 4; rs++) {
        float vap = rap[rs], van = ran[rs], vpc = rpc[rs], vhc = rhc[rs];
        #pragma unroll
        for (int off = 2; off > 0; off >>= 1) {
            vap += __shfl_down_sync(0xffffffffu, vap, off, 4);
            van += __shfl_down_sync(0xffffffffu, van, off, 4);
            vpc += __shfl_down_sync(0xffffffffu, vpc, off, 4);
            vhc += __shfl_down_sync(0xffffffffu, vhc, off, 4);
        }
        if (tig == 0) {
            int rglob = rb + warpM * 32 + (rs >> 1) * 16 + (rs & 1) * 8 + g;
            atomicAdd(&g_ap[rglob], vap);
            atomicAdd(&g_an[rglob], van);
            atomicAdd(&g_pc[rglob], vpc);
            atomicAdd(&g_hc[rglob], vhc);
        }
    }
}

// ---------------------------------------------------------------------------
// finalize: per-row loss, mean over rows (order-invariant under the sort).
// ---------------------------------------------------------------------------
__global__ void finalize_kernel(float* __restrict__ out) {
    __shared__ float s[8];
    const int rows_per_block = Nn / 32;
    int r = blockIdx.x * rows_per_block + threadIdx.x;
    float lap = g_ap[r] / (g_pc[r] + 1e-5f);
    float lan = g_an[r] / (g_hc[r] + 1e-5f);
    float acc = lap + lan;
    #pragma unroll
    for (int off = 16; off > 0; off >>= 1)
        acc += __shfl_down_sync(0xffffffffu, acc, off);
    if ((threadIdx.x & 31) == 0) s[threadIdx.x >> 5] = acc;
    __syncthreads();
    if (threadIdx.x == 0) {
        float b = 0.f;
        #pragma unroll
        for (int i = 0; i < 8; i++) b += s[i];
        atomicAdd(out, b * (1.0f / (float)Nn));
    }
}

// ---------------------------------------------------------------------------
// launch
// ---------------------------------------------------------------------------
extern "C" void kernel_launch(void* const* d_in, const int* in_sizes, int n_in,
                              void* d_out, int out_size) {
    const float* x       = (const float*)d_in[0];
    const int*   labels  = (const int*)d_in[1];
    const float* y       = (const float*)d_in[2];
    const int*   labelsP = (const int*)d_in[3];
    const int*   realL   = (const int*)d_in[6];
    const int*   isReal  = (const int*)d_in[7];
    const float* att     = (const float*)d_in[8];
    float* out = (float*)d_out;

    static bool attr_set = false;
    if (!attr_set) {
        cudaFuncSetAttribute(a2c_main, cudaFuncAttributeMaxDynamicSharedMemorySize,
                             SMEM_TOTAL);
        attr_set = true;
    }

    init_kernel<<<(Nn + 255) / 256, 256>>>(out);
    hist_kernel<<<(Nn + 255) / 256, 256>>>(labels, labelsP);
    scan_kernel<<<1, 1024>>>();
    scatter_kernel<<<(Nn + 255) / 256, 256>>>(labels, labelsP, realL);
    normalize_kernel<<<Nn + Pp, 64>>>(x, y);
    a2c_main<<<ROW_TILES * COL_SPLITS, 256, SMEM_TOTAL>>>(isReal, att);
    finalize_kernel<<<32, 256>>>(out);
}

// round 11
// speedup vs baseline: 1.7769x; 1.1273x over previous
#include <cuda_runtime.h>
#include <cuda_bf16.h>
#include <cstdint>

// ---------------------------------------------------------------------------
// Problem constants
// ---------------------------------------------------------------------------
static constexpr int Nn = 8192;
static constexpr int Pp = 8192;
static constexpr int Dd = 256;   // K
static constexpr int Cc = 1000;

// Tiling
static constexpr int TM = 128;
static constexpr int TN = 128;
static constexpr int ROW_TILES = Nn / TM;                  // 64
static constexpr int COL_TILES = Pp / TN;                  // 64
static constexpr int TOTAL_TILES = ROW_TILES * COL_TILES;  // 4096 (rt-major)
static constexpr int NSM = 148;                            // B200 SM count
static constexpr int NUM_K_STEPS = Dd / 32;                // 8 (32 e4m3 per mma)

// SMEM: tiles are 128 rows x 256 B (fp8), 2 SW128 blocks of [128 x 128B].
static constexpr int TILE_BYTES  = TM * Dd;                // 32768
static constexpr int BLOCK_BYTES = 16384;
static constexpr int SMEM_A  = 0;
static constexpr int SMEM_B0 = SMEM_A + TILE_BYTES;        // 32768
static constexpr int SMEM_B1 = SMEM_B0 + TILE_BYTES;       // 65536
static constexpr int SMEM_LP = SMEM_B1 + TILE_BYTES;       // 98304
static constexpr int SMEM_TOTAL = SMEM_LP + 2 * TN * 4;    // 99328

// ---------------------------------------------------------------------------
// Device scratch
// ---------------------------------------------------------------------------
__device__ uint8_t g_x8[Nn * Dd];   // e4m3 normalized instances (sorted order)
__device__ uint8_t g_y8[Pp * Dd];   // e4m3 normalized proxies  (sorted order)
__device__ float g_ap[Nn];
__device__ float g_an[Nn];
__device__ float g_pc[Nn];
__device__ float g_hc[Nn];
// label-sort scratch
__device__ int g_histx[1024];
__device__ int g_histy[1024];
__device__ int g_offx[1024];
__device__ int g_offy[1024];
__device__ int g_permx[Nn];
__device__ int g_permy[Pp];
__device__ int g_labx[Nn];
__device__ int g_laby[Pp];
__device__ int g_realy[Pp];

// ---------------------------------------------------------------------------
// PTX helpers (compute_100-safe)
// ---------------------------------------------------------------------------
__device__ __forceinline__ uint32_t smem_u32(const void* p) {
    uint32_t a;
    asm("{ .reg .u64 t; cvta.to.shared.u64 t, %1; cvt.u32.u64 %0, t; }" : "=r"(a) : "l"(p));
    return a;
}
__device__ __forceinline__ uint32_t swz128(uint32_t off) {
    return off ^ ((off >> 3) & 0x70);
}
__device__ __forceinline__ void cp_async16(uint32_t dst, const void* src) {
    asm volatile("cp.async.cg.shared.global [%0], [%1], 16;" :: "r"(dst), "l"(src));
}
#define CP_COMMIT()  asm volatile("cp.async.commit_group;" ::: "memory")
#define CP_WAIT(n)   asm volatile("cp.async.wait_group %0;" :: "n"(n) : "memory")

__device__ __forceinline__ void ldsm_x4(uint32_t* r, uint32_t addr) {
    asm volatile("ldmatrix.sync.aligned.m8n8.x4.shared.b16 {%0,%1,%2,%3}, [%4];"
                 : "=r"(r[0]), "=r"(r[1]), "=r"(r[2]), "=r"(r[3]) : "r"(addr));
}
// FP8 e4m3 MMA: m16n8k32, fp32 accumulate. Fragment bytes identical to the
// bf16 m16n8k16 layout, so the same ldmatrix addressing applies.
__device__ __forceinline__ void mma_fp8(float* d, const uint32_t* a,
                                        uint32_t b0, uint32_t b1) {
    asm volatile(
        "mma.sync.aligned.m16n8k32.row.col.f32.e4m3.e4m3.f32 "
        "{%0,%1,%2,%3}, {%4,%5,%6,%7}, {%8,%9}, {%0,%1,%2,%3};"
        : "+f"(d[0]), "+f"(d[1]), "+f"(d[2]), "+f"(d[3])
        : "r"(a[0]), "r"(a[1]), "r"(a[2]), "r"(a[3]), "r"(b0), "r"(b1));
}
__device__ __forceinline__ uint32_t tile_addr(uint32_t base, int row, int kbyte) {
    return base + (kbyte >> 7) * BLOCK_BYTES + swz128(row * 128 + (kbyte & 127));
}
__device__ __forceinline__ uint32_t pack_e4m3x4(float f0, float f1, float f2, float f3) {
    uint16_t lo, hi;
    asm("cvt.rn.satfinite.e4m3x2.f32 %0, %1, %2;" : "=h"(lo) : "f"(f1), "f"(f0));
    asm("cvt.rn.satfinite.e4m3x2.f32 %0, %1, %2;" : "=h"(hi) : "f"(f3), "f"(f2));
    return (uint32_t)lo | ((uint32_t)hi << 16);
}

// ---------------------------------------------------------------------------
// init: zero accumulators + histograms + output
// ---------------------------------------------------------------------------
__global__ void init_kernel(float* __restrict__ out) {
    int i = blockIdx.x * blockDim.x + threadIdx.x;
    if (i < Nn) { g_ap[i] = 0.f; g_an[i] = 0.f; g_pc[i] = 0.f; g_hc[i] = 0.f; }
    if (i < 1024) { g_histx[i] = 0; g_histy[i] = 0; }
    if (i == 0) out[0] = 0.f;
}

// ---------------------------------------------------------------------------
// label histograms
// ---------------------------------------------------------------------------
__global__ void hist_kernel(const int* __restrict__ labels,
                            const int* __restrict__ labelsP) {
    int i = blockIdx.x * blockDim.x + threadIdx.x;
    if (i < Nn) atomicAdd(&g_histx[labels[i]], 1);
    if (i < Pp) atomicAdd(&g_histy[labelsP[i]], 1);
}

// ---------------------------------------------------------------------------
// exclusive scan over 1000 bins (1 block, 1024 threads, Hillis-Steele)
// ---------------------------------------------------------------------------
__global__ void scan_kernel() {
    __shared__ int sx[1024], sy[1024];
    int t = threadIdx.x;
    int hx = (t < Cc) ? g_histx[t] : 0;
    int hy = (t < Cc) ? g_histy[t] : 0;
    sx[t] = hx; sy[t] = hy;
    __syncthreads();
    #pragma unroll
    for (int off = 1; off < 1024; off <<= 1) {
        int vx = (t >= off) ? sx[t - off] : 0;
        int vy = (t >= off) ? sy[t - off] : 0;
        __syncthreads();
        sx[t] += vx; sy[t] += vy;
        __syncthreads();
    }
    if (t < Cc) {
        g_offx[t] = sx[t] - hx;
        g_offy[t] = sy[t] - hy;
    }
}

// ---------------------------------------------------------------------------
// scatter: build permutation + sorted labels / real mask
// ---------------------------------------------------------------------------
__global__ void scatter_kernel(const int* __restrict__ labels,
                               const int* __restrict__ labelsP,
                               const int* __restrict__ realL) {
    int i = blockIdx.x * blockDim.x + threadIdx.x;
    if (i < Nn) {
        int l = labels[i];
        int pos = atomicAdd(&g_offx[l], 1);
        g_permx[pos] = i;
        g_labx[pos] = l;
    }
    if (i < Pp) {
        int l = labelsP[i];
        int pos = atomicAdd(&g_offy[l], 1);
        g_permy[pos] = i;
        g_laby[pos] = l;
        g_realy[pos] = realL[i];
    }
}

// ---------------------------------------------------------------------------
// normalize rows (gathered through the sort permutation) -> e4m3 scratch
// ---------------------------------------------------------------------------
__global__ void normalize_kernel(const float* __restrict__ x,
                                 const float* __restrict__ y) {
    int row = blockIdx.x;
    const float* src;
    uint8_t* dst;
    if (row < Nn) {
        src = x + (size_t)g_permx[row] * Dd;
        dst = g_x8 + (size_t)row * Dd;
    } else {
        int r = row - Nn;
        src = y + (size_t)g_permy[r] * Dd;
        dst = g_y8 + (size_t)r * Dd;
    }
    int t = threadIdx.x; // 0..63
    float4 v = reinterpret_cast<const float4*>(src)[t];
    float ss = v.x * v.x + v.y * v.y + v.z * v.z + v.w * v.w;
    #pragma unroll
    for (int off = 16; off > 0; off >>= 1)
        ss += __shfl_down_sync(0xffffffffu, ss, off);
    __shared__ float s[2];
    if ((t & 31) == 0) s[t >> 5] = ss;
    __syncthreads();
    float inv = 1.0f / fmaxf(sqrtf(s[0] + s[1]), 1e-8f);
    uint32_t pk = pack_e4m3x4(v.x * inv, v.y * inv, v.z * inv, v.w * inv);
    reinterpret_cast<uint32_t*>(dst)[t] = pk;
}

// ---------------------------------------------------------------------------
// Async tile loader: 128 rows x 256 B (fp8) into 2 SW128 blocks. 256 thr x 8.
// ---------------------------------------------------------------------------
__device__ __forceinline__ void load_tile(const uint8_t* gbase, uint32_t sbase) {
    int tid = threadIdx.x;
    #pragma unroll
    for (int it = 0; it < 8; it++) {
        int idx = tid + it * 256;
        int r = idx >> 4;        // row (16 granules of 16B per row)
        int w = idx & 15;        // granule within row
        int c = w >> 3;          // 128B block
        int g = w & 7;           // granule within block row
        const uint8_t* src = gbase + (size_t)r * Dd + w * 16;
        uint32_t dst = sbase + c * BLOCK_BYTES + swz128(r * 128 + g * 16);
        cp_async16(dst, src);
    }
}

// ---------------------------------------------------------------------------
// Main fused kernel: FP8 QMMA GEMM + branchless masked epilogue.
// Grid = 148 CTAs (one per SM); CTA k owns tile-units [k*4096/148,(k+1)*4096/148)
// in rt-major order (tile = rt*64 + ct). Each range spans <= 2 row-tiles.
// 256 threads (8 warps, 4M x 2N). Warp tile 32x64.
// ---------------------------------------------------------------------------
__global__ __launch_bounds__(256)
void a2c_main(const int* __restrict__ isRealPtr,
              const float* __restrict__ att) {
    extern __shared__ __align__(1024) unsigned char smem[];
    const uint32_t sb = smem_u32(smem);
    const int tid = threadIdx.x;
    const int wid = tid >> 5;
    const int lane = tid & 31;
    const int warpM = wid & 3;
    const int warpN = wid >> 2;
    const int g   = lane >> 2;
    const int tig = lane & 3;
    const bool useReal = (isRealPtr[0] != 0);

    int* sLp = reinterpret_cast<int*>(smem + SMEM_LP);

    const int aRow = warpM * 32 + (lane & 15);
    const int bNrow = warpN * 64 + (lane & 7) + ((lane >> 3) & 1) * 8;
    const int kHalf = (lane >> 4) * 16;

    int tileBeg = (blockIdx.x * TOTAL_TILES) / NSM;
    int tileEnd = ((blockIdx.x + 1) * TOTAL_TILES) / NSM;

    int tcur = tileBeg;
    while (tcur < tileEnd) {
        const int rt = tcur >> 6;
        const int ctBeg = tcur & 63;
        int ctEnd = tileEnd - (rt << 6);
        if (ctEnd > COL_TILES) ctEnd = COL_TILES;
        const int rb = rt * TM;

        // ---- segment prologue: A tile + first B tile + its labels ----
        load_tile(g_x8 + (size_t)rb * Dd, sb + SMEM_A);
        load_tile(g_y8 + (size_t)(ctBeg * TN) * Dd,
                  sb + ((ctBeg & 1) ? SMEM_B1 : SMEM_B0));
        CP_COMMIT();
        if (tid < TN) {
            int gc = ctBeg * TN + tid;
            int lp = g_laby[gc];
            if (useReal && g_realy[gc] == 0) lp = -1;
            sLp[(ctBeg & 1) * TN + tid] = lp;
        }

        // per-segment row labels / accumulators
        int liOff4[4];
        int li4[4];
        #pragma unroll
        for (int rs = 0; rs < 4; rs++) {
            int rloc = warpM * 32 + (rs >> 1) * 16 + (rs & 1) * 8 + g;
            li4[rs] = g_labx[rb + rloc];
            liOff4[rs] = li4[rs] * Cc;
        }
        float rap[4] = {0.f, 0.f, 0.f, 0.f};
        float ran[4] = {0.f, 0.f, 0.f, 0.f};
        float rpc[4] = {0.f, 0.f, 0.f, 0.f};
        float rhc[4] = {0.f, 0.f, 0.f, 0.f};

        // A fragments -> registers, once per segment
        CP_WAIT(0);
        __syncthreads();
        uint32_t af[NUM_K_STEPS][2][4];
        #pragma unroll
        for (int ks = 0; ks < NUM_K_STEPS; ks++) {
            const int kb = ks * 32 + kHalf;
            ldsm_x4(af[ks][0], tile_addr(sb + SMEM_A, aRow, kb));
            ldsm_x4(af[ks][1], tile_addr(sb + SMEM_A, aRow + 16, kb));
        }

        for (int ct = ctBeg; ct < ctEnd; ct++) {
            const int buf = ct & 1;
            const uint32_t bsm = sb + (buf ? SMEM_B1 : SMEM_B0);

            CP_WAIT(0);
            __syncthreads();   // tile ct data ready + prev epilogue done

            // prefetch ct+1 (overlaps compute below)
            if (ct + 1 < ctEnd) {
                const uint32_t nb = sb + (((ct + 1) & 1) ? SMEM_B1 : SMEM_B0);
                load_tile(g_y8 + (size_t)((ct + 1) * TN) * Dd, nb);
                CP_COMMIT();
                if (tid < TN) {
                    int gc = (ct + 1) * TN + tid;
                    int lp = g_laby[gc];
                    if (useReal && g_realy[gc] == 0) lp = -1;
                    sLp[((ct + 1) & 1) * TN + tid] = lp;
                }
            }

            // ---- compute 128x128 tile: B from smem, A from registers ----
            float c[2][8][4];
            #pragma unroll
            for (int mt = 0; mt < 2; mt++)
                #pragma unroll
                for (int nt = 0; nt < 8; nt++)
                    #pragma unroll
                    for (int e = 0; e < 4; e++)
                        c[mt][nt][e] = 0.f;

            #pragma unroll
            for (int ks = 0; ks < NUM_K_STEPS; ks++) {
                const int kb = ks * 32 + kHalf;
                uint32_t b[4][4];
                #pragma unroll
                for (int p = 0; p < 4; p++)
                    ldsm_x4(b[p], tile_addr(bsm, bNrow + p * 16, kb));
                #pragma unroll
                for (int mt = 0; mt < 2; mt++)
                    #pragma unroll
                    for (int p = 0; p < 4; p++) {
                        mma_fp8(c[mt][2 * p],     af[ks][mt], b[p][0], b[p][2]);
                        mma_fp8(c[mt][2 * p + 1], af[ks][mt], b[p][1], b[p][3]);
                    }
            }

            // ---- branchless epilogue ----
            const int lpb = buf * TN;
            #pragma unroll
            for (int nt = 0; nt < 8; nt++) {
                const int col0 = warpN * 64 + nt * 8 + 2 * tig;
                const int lp0 = sLp[lpb + col0];
                const int lp1 = sLp[lpb + col0 + 1];
                const int clp0 = lp0 < 0 ? 0 : lp0;
                const int clp1 = lp1 < 0 ? 0 : lp1;
                float av[2][4];
                #pragma unroll
                for (int rs = 0; rs < 4; rs++) {
                    av[0][rs] = __ldg(att + liOff4[rs] + clp0);
                    av[1][rs] = __ldg(att + liOff4[rs] + clp1);
                }
                #pragma unroll
                for (int e = 0; e < 2; e++) {
                    const int lp = e ? lp1 : lp0;
                    const bool valid = (lp >= 0);
                    #pragma unroll
                    for (int mt = 0; mt < 2; mt++)
                        #pragma unroll
                        for (int h = 0; h < 2; h++) {
                            const int rs = mt * 2 + h;
                            const float d = 1.0f - c[mt][nt][h * 2 + e];
                            const float a = av[e][rs] * 0.5f + 0.4f;
                            const bool isPos = valid && (lp == li4[rs]);
                            const bool isHin = valid && (lp != li4[rs]) && (d < a);
                            rap[rs] += isPos ? fmaxf(d - 0.05f, 0.0f) : 0.0f;
                            rpc[rs] += isPos ? 1.0f : 0.0f;
                            ran[rs] += isHin ? (a - d) : 0.0f;
                            rhc[rs] += isHin ? 1.0f : 0.0f;
                        }
                }
            }
        }

        // ---- segment flush: reduce 4 lanes per row, accumulate globally ----
        #pragma unroll
        for (int rs = 0; rs < 4; rs++) {
            float vap = rap[rs], van = ran[rs], vpc = rpc[rs], vhc = rhc[rs];
            #pragma unroll
            for (int off = 2; off > 0; off >>= 1) {
                vap += __shfl_down_sync(0xffffffffu, vap, off, 4);
                van += __shfl_down_sync(0xffffffffu, van, off, 4);
                vpc += __shfl_down_sync(0xffffffffu, vpc, off, 4);
                vhc += __shfl_down_sync(0xffffffffu, vhc, off, 4);
            }
            if (tig == 0) {
                int rglob = rb + warpM * 32 + (rs >> 1) * 16 + (rs & 1) * 8 + g;
                atomicAdd(&g_ap[rglob], vap);
                atomicAdd(&g_an[rglob], van);
                atomicAdd(&g_pc[rglob], vpc);
                atomicAdd(&g_hc[rglob], vhc);
            }
        }

        tcur = (rt << 6) + ctEnd;
        __syncthreads();  // epilogue reads of sLp done before next segment writes
    }
}

// ---------------------------------------------------------------------------
// finalize: per-row loss, mean over rows (order-invariant under the sort).
// ---------------------------------------------------------------------------
__global__ void finalize_kernel(float* __restrict__ out) {
    __shared__ float s[8];
    const int rows_per_block = Nn / 32;
    int r = blockIdx.x * rows_per_block + threadIdx.x;
    float lap = g_ap[r] / (g_pc[r] + 1e-5f);
    float lan = g_an[r] / (g_hc[r] + 1e-5f);
    float acc = lap + lan;
    #pragma unroll
    for (int off = 16; off > 0; off >>= 1)
        acc += __shfl_down_sync(0xffffffffu, acc, off);
    if ((threadIdx.x & 31) == 0) s[threadIdx.x >> 5] = acc;
    __syncthreads();
    if (threadIdx.x == 0) {
        float b = 0.f;
        #pragma unroll
        for (int i = 0; i < 8; i++) b += s[i];
        atomicAdd(out, b * (1.0f / (float)Nn));
    }
}

// ---------------------------------------------------------------------------
// launch
// ---------------------------------------------------------------------------
extern "C" void kernel_launch(void* const* d_in, const int* in_sizes, int n_in,
                              void* d_out, int out_size) {
    const float* x       = (const float*)d_in[0];
    const int*   labels  = (const int*)d_in[1];
    const float* y       = (const float*)d_in[2];
    const int*   labelsP = (const int*)d_in[3];
    const int*   realL   = (const int*)d_in[6];
    const int*   isReal  = (const int*)d_in[7];
    const float* att     = (const float*)d_in[8];
    float* out = (float*)d_out;

    static bool attr_set = false;
    if (!attr_set) {
        cudaFuncSetAttribute(a2c_main, cudaFuncAttributeMaxDynamicSharedMemorySize,
                             SMEM_TOTAL);
        attr_set = true;
    }

    init_kernel<<<(Nn + 255) / 256, 256>>>(out);
    hist_kernel<<<(Nn + 255) / 256, 256>>>(labels, labelsP);
    scan_kernel<<<1, 1024>>>();
    scatter_kernel<<<(Nn + 255) / 256, 256>>>(labels, labelsP, realL);
    normalize_kernel<<<Nn + Pp, 64>>>(x, y);
    a2c_main<<<NSM, 256, SMEM_TOTAL>>>(isReal, att);
    finalize_kernel<<<32, 256>>>(out);
}